// round 5
// baseline (speedup 1.0000x reference)
#include <cuda_runtime.h>
#include <cuda_bf16.h>
#include <cstdint>

// FiberConv collapsed to GEMM: C[400000,384] = x[400000,384] @ Bt^T + bias
//   Bt[n=(t*32+o)][k=(s*32+i)] = sum_a edge[t,s,a] * W[o*32+i, a]
// fp32 accuracy via bf16 split: x=xh+xl, B=Bh+Bl;  xh*Bh + xh*Bl + xl*Bh.
// R5: warp-specialized producer/consumer (8 MMA warps + 4 producer warps),
// 3-stage smem ring, named-barrier handshake. mma.sync.m16n8k16 (sm_103).

#define NDIM 384
#define KDIM 384
#define BATCH 400000

#define BM 128
#define BN 128
#define BK 32
#define NTHREADS 384          // 256 consumer + 128 producer
#define NSTAGES 3
#define NCHUNK (KDIM / BK)    // 12

#define SSTR 40               // padded bf16 row stride (80 bytes)
#define TILE_BYTES (128 * SSTR * 2)        // 10240
#define STAGE_BYTES (4 * TILE_BYTES)       // Ah, Al, Bh, Bl = 40960
#define SMEM_DYN (NSTAGES * STAGE_BYTES)   // 122880

// named barrier ids: FULL(s)=1+s, EMPTY(s)=4+s
#define BAR_FULL(s)  (1 + (s))
#define BAR_EMPTY(s) (4 + (s))

__device__ __nv_bfloat16 g_Bh[NDIM * KDIM];
__device__ __nv_bfloat16 g_Bl[NDIM * KDIM];

__global__ void fiber_precompute(const float* __restrict__ edge,
                                 const float* __restrict__ W) {
    int idx = blockIdx.x * blockDim.x + threadIdx.x;
    if (idx >= NDIM * KDIM) return;
    int n = idx / KDIM, k = idx % KDIM;
    int t = n >> 5, o = n & 31, s = k >> 5, i = k & 31;
    const float* e = edge + (t * 12 + s) * 3;
    const float* w = W + (o * 32 + i) * 3;
    float v = e[0] * w[0] + e[1] * w[1] + e[2] * w[2];
    __nv_bfloat16 h = __float2bfloat16(v);
    __nv_bfloat16 l = __float2bfloat16(v - __bfloat162float(h));
    g_Bh[idx] = h;
    g_Bl[idx] = l;
}

// ---------------- PTX helpers ----------------
__device__ __forceinline__ uint32_t smem_u32(const void* p) {
    uint32_t a;
    asm("{ .reg .u64 t; cvta.to.shared.u64 t, %1; cvt.u32.u64 %0, t; }" : "=r"(a) : "l"(p));
    return a;
}
__device__ __forceinline__ void bar_sync(int id) {
    asm volatile("bar.sync %0, %1;" :: "r"(id), "r"(NTHREADS) : "memory");
}
__device__ __forceinline__ void bar_arrive(int id) {
    asm volatile("bar.arrive %0, %1;" :: "r"(id), "r"(NTHREADS) : "memory");
}
__device__ __forceinline__ void ldsm_x4(uint32_t& r0, uint32_t& r1, uint32_t& r2,
                                        uint32_t& r3, uint32_t addr) {
    asm volatile("ldmatrix.sync.aligned.m8n8.x4.shared.b16 {%0,%1,%2,%3}, [%4];"
                 : "=r"(r0), "=r"(r1), "=r"(r2), "=r"(r3) : "r"(addr));
}
__device__ __forceinline__ void mma_bf16(float& d0, float& d1, float& d2, float& d3,
                                         uint32_t a0, uint32_t a1, uint32_t a2, uint32_t a3,
                                         uint32_t b0, uint32_t b1) {
    asm volatile(
        "mma.sync.aligned.m16n8k16.row.col.f32.bf16.bf16.f32 "
        "{%0,%1,%2,%3}, {%4,%5,%6,%7}, {%8,%9}, {%0,%1,%2,%3};"
        : "+f"(d0), "+f"(d1), "+f"(d2), "+f"(d3)
        : "r"(a0), "r"(a1), "r"(a2), "r"(a3), "r"(b0), "r"(b1));
}
__device__ __forceinline__ void cp_async16(uint32_t dst, const void* src) {
    asm volatile("cp.async.cg.shared.global [%0], [%1], 16;" :: "r"(dst), "l"(src));
}
#define CP_COMMIT() asm volatile("cp.async.commit_group;" ::: "memory")
#define CP_WAIT0()  asm volatile("cp.async.wait_group 0;" ::: "memory")

__device__ __forceinline__ uint32_t pack_hi(float a, float b, uint32_t& lo_out) {
    __nv_bfloat16 ha = __float2bfloat16(a), hb = __float2bfloat16(b);
    __nv_bfloat16 la = __float2bfloat16(a - __bfloat162float(ha));
    __nv_bfloat16 lb = __float2bfloat16(b - __bfloat162float(hb));
    lo_out = ((uint32_t)__bfloat16_as_ushort(lb) << 16) | __bfloat16_as_ushort(la);
    return ((uint32_t)__bfloat16_as_ushort(hb) << 16) | __bfloat16_as_ushort(ha);
}

// ---------------- main GEMM (warp-specialized) ----------------
__global__ void __launch_bounds__(NTHREADS, 1)
fiber_gemm_ws(const float* __restrict__ x, const float* __restrict__ bias,
              float* __restrict__ out) {
    extern __shared__ char smem[];
    const uint32_t sbase = smem_u32(smem);

    const int tid  = threadIdx.x;
    const int bn = blockIdx.x;         // 0..2
    const int bm = blockIdx.y;         // 0..3124

    const float* xblk = x + (size_t)bm * BM * KDIM;

    if (tid >= 256) {
        // =================== PRODUCER (warps 8..11, 128 threads) ===========
        const int p = tid - 256;       // 0..127
        const __nv_bfloat16* gBh = g_Bh + (size_t)bn * BN * KDIM;
        const __nv_bfloat16* gBl = g_Bl + (size_t)bn * BN * KDIM;

        for (int c = 0; c < NCHUNK; c++) {
            const int s = c % NSTAGES;
            if (c >= NSTAGES) bar_sync(BAR_EMPTY(s));

            const uint32_t stage = sbase + s * STAGE_BYTES;
            // --- B via cp.async: 512 16B segs per part, 4 per lane ---
            {
                uint32_t dBh = stage + 2 * TILE_BYTES;
                uint32_t dBl = dBh + TILE_BYTES;
                #pragma unroll
                for (int it = 0; it < 4; it++) {
                    int slot = it * 128 + p;            // 0..511
                    int r = slot >> 2, seg = slot & 3;
                    uint32_t doff = (uint32_t)(r * (SSTR * 2) + seg * 16);
                    size_t goff = (size_t)r * KDIM + c * BK + seg * 8;
                    cp_async16(dBh + doff, gBh + goff);
                    cp_async16(dBl + doff, gBl + goff);
                }
                CP_COMMIT();
            }
            // --- x: LDG fp32, split, STS (8 float4 per lane) ---
            {
                float4 v[8];
                #pragma unroll
                for (int it = 0; it < 8; it++) {
                    int slot = it * 128 + p;            // 0..1023
                    int r = slot >> 3, c4 = (slot & 7) * 4;
                    v[it] = *(const float4*)(xblk + (size_t)r * KDIM + c * BK + c4);
                }
                uint32_t dAh = stage;
                uint32_t dAl = stage + TILE_BYTES;
                #pragma unroll
                for (int it = 0; it < 8; it++) {
                    int slot = it * 128 + p;
                    int r = slot >> 3, c4 = (slot & 7) * 4;
                    uint32_t lo01, lo23;
                    uint32_t h01 = pack_hi(v[it].x, v[it].y, lo01);
                    uint32_t h23 = pack_hi(v[it].z, v[it].w, lo23);
                    uint32_t doff = (uint32_t)(r * (SSTR * 2) + c4 * 2);
                    asm volatile("st.shared.v2.b32 [%0], {%1,%2};"
                                 :: "r"(dAh + doff), "r"(h01), "r"(h23));
                    asm volatile("st.shared.v2.b32 [%0], {%1,%2};"
                                 :: "r"(dAl + doff), "r"(lo01), "r"(lo23));
                }
            }
            CP_WAIT0();
            bar_arrive(BAR_FULL(s));
        }
        return;
    }

    // ===================== CONSUMER (warps 0..7, 256 threads) ==============
    const int lane = tid & 31;
    const int warp = tid >> 5;
    const int wm = warp >> 2;          // 0..1
    const int wn = warp & 3;           // 0..3

    float acc[4][4][4];
    #pragma unroll
    for (int a = 0; a < 4; a++)
        #pragma unroll
        for (int b = 0; b < 4; b++)
            #pragma unroll
            for (int c = 0; c < 4; c++) acc[a][b][c] = 0.f;

    const uint32_t a_lane_off = (uint32_t)((wm * 64 + (lane & 15)) * (SSTR * 2) + (lane >> 4) * 16);
    const uint32_t b_lane_off = (uint32_t)((wn * 32 + ((lane >> 4) << 3) + (lane & 7)) * (SSTR * 2)
                                           + ((lane >> 3) & 1) * 16);

    for (int c = 0; c < NCHUNK; c++) {
        const int s = c % NSTAGES;
        bar_sync(BAR_FULL(s));

        const uint32_t Ah = sbase + s * STAGE_BYTES;
        const uint32_t Al = Ah + TILE_BYTES;
        const uint32_t Bh = Ah + 2 * TILE_BYTES;
        const uint32_t Bl = Ah + 3 * TILE_BYTES;

        #pragma unroll
        for (int ks = 0; ks < BK / 16; ks++) {
            const uint32_t kso = ks * 32;
            uint32_t af[4][4], bh[2][4], bl[2][4];
            #pragma unroll
            for (int mi = 0; mi < 4; mi++)
                ldsm_x4(af[mi][0], af[mi][1], af[mi][2], af[mi][3],
                        Ah + a_lane_off + mi * 16 * (SSTR * 2) + kso);
            #pragma unroll
            for (int pj = 0; pj < 2; pj++)
                ldsm_x4(bh[pj][0], bh[pj][1], bh[pj][2], bh[pj][3],
                        Bh + b_lane_off + pj * 16 * (SSTR * 2) + kso);
            #pragma unroll
            for (int pj = 0; pj < 2; pj++)
                ldsm_x4(bl[pj][0], bl[pj][1], bl[pj][2], bl[pj][3],
                        Bl + b_lane_off + pj * 16 * (SSTR * 2) + kso);

            // pass 1: Ah * Bh
            #pragma unroll
            for (int mi = 0; mi < 4; mi++)
                #pragma unroll
                for (int ni = 0; ni < 4; ni++)
                    mma_bf16(acc[mi][ni][0], acc[mi][ni][1], acc[mi][ni][2], acc[mi][ni][3],
                             af[mi][0], af[mi][1], af[mi][2], af[mi][3],
                             bh[ni >> 1][(ni & 1) * 2], bh[ni >> 1][(ni & 1) * 2 + 1]);
            // pass 2: Ah * Bl
            #pragma unroll
            for (int mi = 0; mi < 4; mi++)
                #pragma unroll
                for (int ni = 0; ni < 4; ni++)
                    mma_bf16(acc[mi][ni][0], acc[mi][ni][1], acc[mi][ni][2], acc[mi][ni][3],
                             af[mi][0], af[mi][1], af[mi][2], af[mi][3],
                             bl[ni >> 1][(ni & 1) * 2], bl[ni >> 1][(ni & 1) * 2 + 1]);
            // pass 3: Al * Bh (reload A frags into af)
            #pragma unroll
            for (int mi = 0; mi < 4; mi++)
                ldsm_x4(af[mi][0], af[mi][1], af[mi][2], af[mi][3],
                        Al + a_lane_off + mi * 16 * (SSTR * 2) + kso);
            #pragma unroll
            for (int mi = 0; mi < 4; mi++)
                #pragma unroll
                for (int ni = 0; ni < 4; ni++)
                    mma_bf16(acc[mi][ni][0], acc[mi][ni][1], acc[mi][ni][2], acc[mi][ni][3],
                             af[mi][0], af[mi][1], af[mi][2], af[mi][3],
                             bh[ni >> 1][(ni & 1) * 2], bh[ni >> 1][(ni & 1) * 2 + 1]);
        }

        bar_arrive(BAR_EMPTY(s));
    }

    // ---- epilogue: registers -> global (float2 stores) + bias ----
    float* oblk = out + (size_t)bm * BM * NDIM + bn * BN;
    const int r0 = wm * 64 + (lane >> 2);
    const int c0 = wn * 32 + (lane & 3) * 2;
    #pragma unroll
    for (int ni = 0; ni < 4; ni++) {
        const int col = c0 + ni * 8;
        const float b0 = bias[col & 31];
        const float b1 = bias[(col + 1) & 31];
        #pragma unroll
        for (int mi = 0; mi < 4; mi++) {
            const int row = r0 + mi * 16;
            float2 v0 = make_float2(acc[mi][ni][0] + b0, acc[mi][ni][1] + b1);
            float2 v1 = make_float2(acc[mi][ni][2] + b0, acc[mi][ni][3] + b1);
            *(float2*)(oblk + (size_t)row * NDIM + col) = v0;
            *(float2*)(oblk + (size_t)(row + 8) * NDIM + col) = v1;
        }
    }
}

// ---------------------------------------------------------------------------
extern "C" void kernel_launch(void* const* d_in, const int* in_sizes, int n_in,
                              void* d_out, int out_size) {
    const float* x    = (const float*)d_in[0];   // [400000, 384]
    const float* edge = (const float*)d_in[1];   // [12, 12, 3]
    const float* W    = (const float*)d_in[2];   // [1024, 3]
    const float* bias = (const float*)d_in[3];   // [32]
    float* out = (float*)d_out;                  // [400000, 384]

    cudaFuncSetAttribute(fiber_gemm_ws,
                         cudaFuncAttributeMaxDynamicSharedMemorySize, SMEM_DYN);

    fiber_precompute<<<(NDIM * KDIM + 255) / 256, 256>>>(edge, W);

    dim3 grid(NDIM / BN, BATCH / BM);   // (3, 3125)
    fiber_gemm_ws<<<grid, NTHREADS, SMEM_DYN>>>(x, bias, out);
}

// round 6
// speedup vs baseline: 1.6022x; 1.6022x over previous
#include <cuda_runtime.h>
#include <cuda_fp16.h>
#include <cstdint>

// FiberConv collapsed to GEMM: C[400000,384] = x[400000,384] @ Bt^T + bias
//   Bt[n=(t*32+o)][k=(s*32+i)] = sum_a edge[t,s,a] * W[o*32+i, a]
// R6: fp16 2-term split (Markidis): x = xh + xl (fp16 pair, exact to ~2^-22),
//     B -> Bh (fp16).  C ~= xh*Bh + xl*Bh = x*Bh.  Neglected x*Bl ~ 3e-4 rel.
// Structure = R4 (best so far): homogeneous warps, 2 CTAs/SM, double buffer,
// 3 separated MMA passes -> now 2 passes. mma.sync.m16n8k16.f16.

#define NDIM 384
#define KDIM 384
#define BATCH 400000

#define BM 128
#define BN 128
#define BK 32
#define NTHREADS 256

#define SSTR 40                            // padded fp16 row stride (80 bytes)
#define TILE_BYTES (128 * SSTR * 2)        // 10240
#define STAGE_BYTES (3 * TILE_BYTES)       // Ah, Al, Bh = 30720
#define SMEM_DYN (2 * STAGE_BYTES)         // 61440

__device__ __half g_Bh[NDIM * KDIM];

__global__ void fiber_precompute(const float* __restrict__ edge,
                                 const float* __restrict__ W) {
    int idx = blockIdx.x * blockDim.x + threadIdx.x;
    if (idx >= NDIM * KDIM) return;
    int n = idx / KDIM, k = idx % KDIM;
    int t = n >> 5, o = n & 31, s = k >> 5, i = k & 31;
    const float* e = edge + (t * 12 + s) * 3;
    const float* w = W + (o * 32 + i) * 3;
    float v = e[0] * w[0] + e[1] * w[1] + e[2] * w[2];
    g_Bh[idx] = __float2half_rn(v);
}

// ---------------- PTX helpers ----------------
__device__ __forceinline__ uint32_t smem_u32(const void* p) {
    uint32_t a;
    asm("{ .reg .u64 t; cvta.to.shared.u64 t, %1; cvt.u32.u64 %0, t; }" : "=r"(a) : "l"(p));
    return a;
}
__device__ __forceinline__ void ldsm_x4(uint32_t& r0, uint32_t& r1, uint32_t& r2,
                                        uint32_t& r3, uint32_t addr) {
    asm volatile("ldmatrix.sync.aligned.m8n8.x4.shared.b16 {%0,%1,%2,%3}, [%4];"
                 : "=r"(r0), "=r"(r1), "=r"(r2), "=r"(r3) : "r"(addr));
}
__device__ __forceinline__ void mma_f16(float& d0, float& d1, float& d2, float& d3,
                                        uint32_t a0, uint32_t a1, uint32_t a2, uint32_t a3,
                                        uint32_t b0, uint32_t b1) {
    asm volatile(
        "mma.sync.aligned.m16n8k16.row.col.f32.f16.f16.f32 "
        "{%0,%1,%2,%3}, {%4,%5,%6,%7}, {%8,%9}, {%0,%1,%2,%3};"
        : "+f"(d0), "+f"(d1), "+f"(d2), "+f"(d3)
        : "r"(a0), "r"(a1), "r"(a2), "r"(a3), "r"(b0), "r"(b1));
}
__device__ __forceinline__ void cp_async16(uint32_t dst, const void* src) {
    asm volatile("cp.async.cg.shared.global [%0], [%1], 16;" :: "r"(dst), "l"(src));
}
#define CP_COMMIT() asm volatile("cp.async.commit_group;" ::: "memory")
#define CP_WAIT0()  asm volatile("cp.async.wait_group 0;" ::: "memory")

__device__ __forceinline__ uint32_t pack_hi(float a, float b, uint32_t& lo_out) {
    __half ha = __float2half_rn(a), hb = __float2half_rn(b);
    __half la = __float2half_rn(a - __half2float(ha));
    __half lb = __float2half_rn(b - __half2float(hb));
    lo_out = ((uint32_t)__half_as_ushort(lb) << 16) | __half_as_ushort(la);
    return ((uint32_t)__half_as_ushort(hb) << 16) | __half_as_ushort(ha);
}

// ---------------- main GEMM ----------------
__global__ void __launch_bounds__(NTHREADS, 2)
fiber_gemm_hmma(const float* __restrict__ x, const float* __restrict__ bias,
                float* __restrict__ out) {
    extern __shared__ char smem[];
    const uint32_t sbase = smem_u32(smem);

    const int tid  = threadIdx.x;
    const int lane = tid & 31;
    const int warp = tid >> 5;
    const int wm = warp >> 2;          // 0..1
    const int wn = warp & 3;           // 0..3
    const int bn = blockIdx.x;         // 0..2
    const int bm = blockIdx.y;         // 0..3124

    const float* xblk = x + (size_t)bm * BM * KDIM;
    const __half* gBh = g_Bh + (size_t)bn * BN * KDIM;

    float acc[4][4][4];
    #pragma unroll
    for (int a = 0; a < 4; a++)
        #pragma unroll
        for (int b = 0; b < 4; b++)
            #pragma unroll
            for (int c = 0; c < 4; c++) acc[a][b][c] = 0.f;

    const uint32_t a_lane_off = (uint32_t)((wm * 64 + (lane & 15)) * (SSTR * 2) + (lane >> 4) * 16);
    const uint32_t b_lane_off = (uint32_t)((wn * 32 + ((lane >> 4) << 3) + (lane & 7)) * (SSTR * 2)
                                           + ((lane >> 3) & 1) * 16);

    float4 xr[4];

    auto load_x = [&](int c) {
        #pragma unroll
        for (int it = 0; it < 4; it++) {
            int slot = it * NTHREADS + tid;
            int r = slot >> 3, c4 = (slot & 7) * 4;
            xr[it] = *(const float4*)(xblk + (size_t)r * KDIM + c * BK + c4);
        }
    };
    auto cp_B = [&](int c, int buf) {
        uint32_t dBh = sbase + buf * STAGE_BYTES + 2 * TILE_BYTES;
        #pragma unroll
        for (int it = 0; it < 2; it++) {
            int slot = it * NTHREADS + tid;
            int r = slot >> 2, seg = slot & 3;
            uint32_t doff = (uint32_t)(r * (SSTR * 2) + seg * 16);
            size_t goff = (size_t)r * KDIM + c * BK + seg * 8;
            cp_async16(dBh + doff, gBh + goff);
        }
        CP_COMMIT();
    };
    auto sts_x = [&](int buf) {
        uint32_t dAh = sbase + buf * STAGE_BYTES;
        uint32_t dAl = dAh + TILE_BYTES;
        #pragma unroll
        for (int it = 0; it < 4; it++) {
            int slot = it * NTHREADS + tid;
            int r = slot >> 3, c4 = (slot & 7) * 4;
            uint32_t lo01, lo23;
            uint32_t h01 = pack_hi(xr[it].x, xr[it].y, lo01);
            uint32_t h23 = pack_hi(xr[it].z, xr[it].w, lo23);
            uint32_t doff = (uint32_t)(r * (SSTR * 2) + c4 * 2);
            asm volatile("st.shared.v2.b32 [%0], {%1,%2};" :: "r"(dAh + doff), "r"(h01), "r"(h23));
            asm volatile("st.shared.v2.b32 [%0], {%1,%2};" :: "r"(dAl + doff), "r"(lo01), "r"(lo23));
        }
    };

    load_x(0);
    cp_B(0, 0);
    sts_x(0);
    CP_WAIT0();
    __syncthreads();

    const int NCHUNK = KDIM / BK;   // 12
    for (int c = 0; c < NCHUNK; c++) {
        const int buf = c & 1;
        if (c + 1 < NCHUNK) {
            load_x(c + 1);
            cp_B(c + 1, buf ^ 1);
        }

        const uint32_t Ah = sbase + buf * STAGE_BYTES;
        const uint32_t Al = Ah + TILE_BYTES;
        const uint32_t Bh = Ah + 2 * TILE_BYTES;

        #pragma unroll
        for (int ks = 0; ks < BK / 16; ks++) {
            const uint32_t kso = ks * 32;
            uint32_t af[4][4], bh[2][4];
            #pragma unroll
            for (int mi = 0; mi < 4; mi++)
                ldsm_x4(af[mi][0], af[mi][1], af[mi][2], af[mi][3],
                        Ah + a_lane_off + mi * 16 * (SSTR * 2) + kso);
            #pragma unroll
            for (int pj = 0; pj < 2; pj++)
                ldsm_x4(bh[pj][0], bh[pj][1], bh[pj][2], bh[pj][3],
                        Bh + b_lane_off + pj * 16 * (SSTR * 2) + kso);

            // pass 1: Ah * Bh — 16 independent MMAs
            #pragma unroll
            for (int mi = 0; mi < 4; mi++)
                #pragma unroll
                for (int ni = 0; ni < 4; ni++)
                    mma_f16(acc[mi][ni][0], acc[mi][ni][1], acc[mi][ni][2], acc[mi][ni][3],
                            af[mi][0], af[mi][1], af[mi][2], af[mi][3],
                            bh[ni >> 1][(ni & 1) * 2], bh[ni >> 1][(ni & 1) * 2 + 1]);

            // pass 2: Al * Bh — reload A frags (each acc re-touched 16 MMAs later)
            #pragma unroll
            for (int mi = 0; mi < 4; mi++)
                ldsm_x4(af[mi][0], af[mi][1], af[mi][2], af[mi][3],
                        Al + a_lane_off + mi * 16 * (SSTR * 2) + kso);
            #pragma unroll
            for (int mi = 0; mi < 4; mi++)
                #pragma unroll
                for (int ni = 0; ni < 4; ni++)
                    mma_f16(acc[mi][ni][0], acc[mi][ni][1], acc[mi][ni][2], acc[mi][ni][3],
                            af[mi][0], af[mi][1], af[mi][2], af[mi][3],
                            bh[ni >> 1][(ni & 1) * 2], bh[ni >> 1][(ni & 1) * 2 + 1]);
        }

        if (c + 1 < NCHUNK) {
            sts_x(buf ^ 1);
            CP_WAIT0();
        }
        __syncthreads();
    }

    // ---- epilogue: registers -> global (float2 stores) + bias ----
    float* oblk = out + (size_t)bm * BM * NDIM + bn * BN;
    const int r0 = wm * 64 + (lane >> 2);
    const int c0 = wn * 32 + (lane & 3) * 2;
    #pragma unroll
    for (int ni = 0; ni < 4; ni++) {
        const int col = c0 + ni * 8;
        const float b0 = bias[col & 31];
        const float b1 = bias[(col + 1) & 31];
        #pragma unroll
        for (int mi = 0; mi < 4; mi++) {
            const int row = r0 + mi * 16;
            float2 v0 = make_float2(acc[mi][ni][0] + b0, acc[mi][ni][1] + b1);
            float2 v1 = make_float2(acc[mi][ni][2] + b0, acc[mi][ni][3] + b1);
            *(float2*)(oblk + (size_t)row * NDIM + col) = v0;
            *(float2*)(oblk + (size_t)(row + 8) * NDIM + col) = v1;
        }
    }
}

// ---------------------------------------------------------------------------
extern "C" void kernel_launch(void* const* d_in, const int* in_sizes, int n_in,
                              void* d_out, int out_size) {
    const float* x    = (const float*)d_in[0];   // [400000, 384]
    const float* edge = (const float*)d_in[1];   // [12, 12, 3]
    const float* W    = (const float*)d_in[2];   // [1024, 3]
    const float* bias = (const float*)d_in[3];   // [32]
    float* out = (float*)d_out;                  // [400000, 384]

    cudaFuncSetAttribute(fiber_gemm_hmma,
                         cudaFuncAttributeMaxDynamicSharedMemorySize, SMEM_DYN);

    fiber_precompute<<<(NDIM * KDIM + 255) / 256, 256>>>(edge, W);

    dim3 grid(NDIM / BN, BATCH / BM);   // (3, 3125)
    fiber_gemm_hmma<<<grid, NTHREADS, SMEM_DYN>>>(x, bias, out);
}

// round 7
// speedup vs baseline: 1.6140x; 1.0074x over previous
#include <cuda_runtime.h>
#include <cuda_fp16.h>
#include <cstdint>

// FiberConv collapsed to GEMM: C[400000,384] = x[400000,384] @ Bt^T + bias
//   Bt[n=(t*32+o)][k=(s*32+i)] = sum_a edge[t,s,a] * W[o*32+i, a]
// R7: split flipped to B side:  x -> xh (fp16, one rounding),
//     B = Bh + Bl (fp16 hi/lo, precomputed).  C ~= xh*Bh + xh*Bl = xh*B.
//     Neglected xl*B ~ 2e-4 rel (same class as R6's measured 2.08e-4).
// Benefit: A fragments are loaded ONCE per k-slice and reused by both MMA
// passes (ldsm 10 -> 8 per slice; L1 pipe was 66% > tensor 54%), and the
// producer path halves (no xl computation, half the STS).

#define NDIM 384
#define KDIM 384
#define BATCH 400000

#define BM 128
#define BN 128
#define BK 32
#define NTHREADS 256

#define SSTR 40                            // padded fp16 row stride (80 bytes)
#define TILE_BYTES (128 * SSTR * 2)        // 10240
#define STAGE_BYTES (3 * TILE_BYTES)       // Ah, Bh, Bl = 30720
#define SMEM_DYN (2 * STAGE_BYTES)         // 61440

__device__ __half g_Bh[NDIM * KDIM];
__device__ __half g_Bl[NDIM * KDIM];

__global__ void fiber_precompute(const float* __restrict__ edge,
                                 const float* __restrict__ W) {
    int idx = blockIdx.x * blockDim.x + threadIdx.x;
    if (idx >= NDIM * KDIM) return;
    int n = idx / KDIM, k = idx % KDIM;
    int t = n >> 5, o = n & 31, s = k >> 5, i = k & 31;
    const float* e = edge + (t * 12 + s) * 3;
    const float* w = W + (o * 32 + i) * 3;
    float v = e[0] * w[0] + e[1] * w[1] + e[2] * w[2];
    __half h = __float2half_rn(v);
    __half l = __float2half_rn(v - __half2float(h));
    g_Bh[idx] = h;
    g_Bl[idx] = l;
}

// ---------------- PTX helpers ----------------
__device__ __forceinline__ uint32_t smem_u32(const void* p) {
    uint32_t a;
    asm("{ .reg .u64 t; cvta.to.shared.u64 t, %1; cvt.u32.u64 %0, t; }" : "=r"(a) : "l"(p));
    return a;
}
__device__ __forceinline__ void ldsm_x4(uint32_t& r0, uint32_t& r1, uint32_t& r2,
                                        uint32_t& r3, uint32_t addr) {
    asm volatile("ldmatrix.sync.aligned.m8n8.x4.shared.b16 {%0,%1,%2,%3}, [%4];"
                 : "=r"(r0), "=r"(r1), "=r"(r2), "=r"(r3) : "r"(addr));
}
__device__ __forceinline__ void mma_f16(float& d0, float& d1, float& d2, float& d3,
                                        uint32_t a0, uint32_t a1, uint32_t a2, uint32_t a3,
                                        uint32_t b0, uint32_t b1) {
    asm volatile(
        "mma.sync.aligned.m16n8k16.row.col.f32.f16.f16.f32 "
        "{%0,%1,%2,%3}, {%4,%5,%6,%7}, {%8,%9}, {%0,%1,%2,%3};"
        : "+f"(d0), "+f"(d1), "+f"(d2), "+f"(d3)
        : "r"(a0), "r"(a1), "r"(a2), "r"(a3), "r"(b0), "r"(b1));
}
__device__ __forceinline__ void cp_async16(uint32_t dst, const void* src) {
    asm volatile("cp.async.cg.shared.global [%0], [%1], 16;" :: "r"(dst), "l"(src));
}
#define CP_COMMIT() asm volatile("cp.async.commit_group;" ::: "memory")
#define CP_WAIT0()  asm volatile("cp.async.wait_group 0;" ::: "memory")

__device__ __forceinline__ uint32_t pack2h(float a, float b) {
    __half ha = __float2half_rn(a), hb = __float2half_rn(b);
    return ((uint32_t)__half_as_ushort(hb) << 16) | __half_as_ushort(ha);
}

// ---------------- main GEMM ----------------
__global__ void __launch_bounds__(NTHREADS, 2)
fiber_gemm_hmma(const float* __restrict__ x, const float* __restrict__ bias,
                float* __restrict__ out) {
    extern __shared__ char smem[];
    const uint32_t sbase = smem_u32(smem);

    const int tid  = threadIdx.x;
    const int lane = tid & 31;
    const int warp = tid >> 5;
    const int wm = warp >> 2;          // 0..1
    const int wn = warp & 3;           // 0..3
    const int bn = blockIdx.x;         // 0..2
    const int bm = blockIdx.y;         // 0..3124

    const float* xblk = x + (size_t)bm * BM * KDIM;
    const __half* gBh = g_Bh + (size_t)bn * BN * KDIM;
    const __half* gBl = g_Bl + (size_t)bn * BN * KDIM;

    float acc[4][4][4];
    #pragma unroll
    for (int a = 0; a < 4; a++)
        #pragma unroll
        for (int b = 0; b < 4; b++)
            #pragma unroll
            for (int c = 0; c < 4; c++) acc[a][b][c] = 0.f;

    const uint32_t a_lane_off = (uint32_t)((wm * 64 + (lane & 15)) * (SSTR * 2) + (lane >> 4) * 16);
    const uint32_t b_lane_off = (uint32_t)((wn * 32 + ((lane >> 4) << 3) + (lane & 7)) * (SSTR * 2)
                                           + ((lane >> 3) & 1) * 16);

    float4 xr[4];

    auto load_x = [&](int c) {
        #pragma unroll
        for (int it = 0; it < 4; it++) {
            int slot = it * NTHREADS + tid;
            int r = slot >> 3, c4 = (slot & 7) * 4;
            xr[it] = *(const float4*)(xblk + (size_t)r * KDIM + c * BK + c4);
        }
    };
    auto cp_B = [&](int c, int buf) {
        uint32_t dBh = sbase + buf * STAGE_BYTES + TILE_BYTES;
        uint32_t dBl = dBh + TILE_BYTES;
        #pragma unroll
        for (int it = 0; it < 2; it++) {
            int slot = it * NTHREADS + tid;
            int r = slot >> 2, seg = slot & 3;
            uint32_t doff = (uint32_t)(r * (SSTR * 2) + seg * 16);
            size_t goff = (size_t)r * KDIM + c * BK + seg * 8;
            cp_async16(dBh + doff, gBh + goff);
            cp_async16(dBl + doff, gBl + goff);
        }
        CP_COMMIT();
    };
    auto sts_x = [&](int buf) {
        uint32_t dAh = sbase + buf * STAGE_BYTES;
        #pragma unroll
        for (int it = 0; it < 4; it++) {
            int slot = it * NTHREADS + tid;
            int r = slot >> 3, c4 = (slot & 7) * 4;
            uint32_t h01 = pack2h(xr[it].x, xr[it].y);
            uint32_t h23 = pack2h(xr[it].z, xr[it].w);
            uint32_t doff = (uint32_t)(r * (SSTR * 2) + c4 * 2);
            asm volatile("st.shared.v2.b32 [%0], {%1,%2};" :: "r"(dAh + doff), "r"(h01), "r"(h23));
        }
    };

    load_x(0);
    cp_B(0, 0);
    sts_x(0);
    CP_WAIT0();
    __syncthreads();

    const int NCHUNK = KDIM / BK;   // 12
    for (int c = 0; c < NCHUNK; c++) {
        const int buf = c & 1;
        if (c + 1 < NCHUNK) {
            load_x(c + 1);
            cp_B(c + 1, buf ^ 1);
        }

        const uint32_t Ah = sbase + buf * STAGE_BYTES;
        const uint32_t Bh = Ah + TILE_BYTES;
        const uint32_t Bl = Ah + 2 * TILE_BYTES;

        #pragma unroll
        for (int ks = 0; ks < BK / 16; ks++) {
            const uint32_t kso = ks * 32;
            uint32_t af[4][4], bh[2][4], bl[2][4];
            #pragma unroll
            for (int mi = 0; mi < 4; mi++)
                ldsm_x4(af[mi][0], af[mi][1], af[mi][2], af[mi][3],
                        Ah + a_lane_off + mi * 16 * (SSTR * 2) + kso);
            #pragma unroll
            for (int pj = 0; pj < 2; pj++)
                ldsm_x4(bh[pj][0], bh[pj][1], bh[pj][2], bh[pj][3],
                        Bh + b_lane_off + pj * 16 * (SSTR * 2) + kso);
            #pragma unroll
            for (int pj = 0; pj < 2; pj++)
                ldsm_x4(bl[pj][0], bl[pj][1], bl[pj][2], bl[pj][3],
                        Bl + b_lane_off + pj * 16 * (SSTR * 2) + kso);

            // pass 1: Ah * Bh — 16 independent MMAs
            #pragma unroll
            for (int mi = 0; mi < 4; mi++)
                #pragma unroll
                for (int ni = 0; ni < 4; ni++)
                    mma_f16(acc[mi][ni][0], acc[mi][ni][1], acc[mi][ni][2], acc[mi][ni][3],
                            af[mi][0], af[mi][1], af[mi][2], af[mi][3],
                            bh[ni >> 1][(ni & 1) * 2], bh[ni >> 1][(ni & 1) * 2 + 1]);

            // pass 2: Ah * Bl — same A fragments, no reload
            #pragma unroll
            for (int mi = 0; mi < 4; mi++)
                #pragma unroll
                for (int ni = 0; ni < 4; ni++)
                    mma_f16(acc[mi][ni][0], acc[mi][ni][1], acc[mi][ni][2], acc[mi][ni][3],
                            af[mi][0], af[mi][1], af[mi][2], af[mi][3],
                            bl[ni >> 1][(ni & 1) * 2], bl[ni >> 1][(ni & 1) * 2 + 1]);
        }

        if (c + 1 < NCHUNK) {
            sts_x(buf ^ 1);
            CP_WAIT0();
        }
        __syncthreads();
    }

    // ---- epilogue: registers -> global (float2 stores) + bias ----
    float* oblk = out + (size_t)bm * BM * NDIM + bn * BN;
    const int r0 = wm * 64 + (lane >> 2);
    const int c0 = wn * 32 + (lane & 3) * 2;
    #pragma unroll
    for (int ni = 0; ni < 4; ni++) {
        const int col = c0 + ni * 8;
        const float b0 = bias[col & 31];
        const float b1 = bias[(col + 1) & 31];
        #pragma unroll
        for (int mi = 0; mi < 4; mi++) {
            const int row = r0 + mi * 16;
            float2 v0 = make_float2(acc[mi][ni][0] + b0, acc[mi][ni][1] + b1);
            float2 v1 = make_float2(acc[mi][ni][2] + b0, acc[mi][ni][3] + b1);
            *(float2*)(oblk + (size_t)row * NDIM + col) = v0;
            *(float2*)(oblk + (size_t)(row + 8) * NDIM + col) = v1;
        }
    }
}

// ---------------------------------------------------------------------------
extern "C" void kernel_launch(void* const* d_in, const int* in_sizes, int n_in,
                              void* d_out, int out_size) {
    const float* x    = (const float*)d_in[0];   // [400000, 384]
    const float* edge = (const float*)d_in[1];   // [12, 12, 3]
    const float* W    = (const float*)d_in[2];   // [1024, 3]
    const float* bias = (const float*)d_in[3];   // [32]
    float* out = (float*)d_out;                  // [400000, 384]

    cudaFuncSetAttribute(fiber_gemm_hmma,
                         cudaFuncAttributeMaxDynamicSharedMemorySize, SMEM_DYN);

    fiber_precompute<<<(NDIM * KDIM + 255) / 256, 256>>>(edge, W);

    dim3 grid(NDIM / BN, BATCH / BM);   // (3, 3125)
    fiber_gemm_hmma<<<grid, NTHREADS, SMEM_DYN>>>(x, bias, out);
}

// round 8
// speedup vs baseline: 1.8886x; 1.1701x over previous
#include <cuda_runtime.h>
#include <cuda_fp16.h>
#include <cstdint>

// FiberConv collapsed to GEMM: C[400000,384] = x[400000,384] @ Bt^T + bias
//   Bt[n=(t*32+o)][k=(s*32+i)] = sum_a edge[t,s,a] * W[o*32+i, a]
// R8: single-pass fp16 (xh * Bh). Calibrated error model: each neglected
// low-order term contributes ~2.08e-4 rel (measured R6/R7); both together
// ~2.9e-4 RMS — 3.4x margin under the 1e-3 gate. Halves the MMA work.
// Pipeline: 3-stage smem ring, cp.async B prefetch 2 chunks ahead,
// wait_group 1 before the barrier (newest group stays in flight).

#define NDIM 384
#define KDIM 384
#define BATCH 400000

#define BM 128
#define BN 128
#define BK 32
#define NTHREADS 256
#define NSTAGES 3
#define NCHUNK (KDIM / BK)                 // 12

#define SSTR 40                            // padded fp16 row stride (80 bytes)
#define TILE_BYTES (128 * SSTR * 2)        // 10240
#define STAGE_BYTES (2 * TILE_BYTES)       // Ah, Bh = 20480
#define SMEM_DYN (NSTAGES * STAGE_BYTES)   // 61440

__device__ __half g_Bh[NDIM * KDIM];

__global__ void fiber_precompute(const float* __restrict__ edge,
                                 const float* __restrict__ W) {
    int idx = blockIdx.x * blockDim.x + threadIdx.x;
    if (idx >= NDIM * KDIM) return;
    int n = idx / KDIM, k = idx % KDIM;
    int t = n >> 5, o = n & 31, s = k >> 5, i = k & 31;
    const float* e = edge + (t * 12 + s) * 3;
    const float* w = W + (o * 32 + i) * 3;
    float v = e[0] * w[0] + e[1] * w[1] + e[2] * w[2];
    g_Bh[idx] = __float2half_rn(v);
}

// ---------------- PTX helpers ----------------
__device__ __forceinline__ uint32_t smem_u32(const void* p) {
    uint32_t a;
    asm("{ .reg .u64 t; cvta.to.shared.u64 t, %1; cvt.u32.u64 %0, t; }" : "=r"(a) : "l"(p));
    return a;
}
__device__ __forceinline__ void ldsm_x4(uint32_t& r0, uint32_t& r1, uint32_t& r2,
                                        uint32_t& r3, uint32_t addr) {
    asm volatile("ldmatrix.sync.aligned.m8n8.x4.shared.b16 {%0,%1,%2,%3}, [%4];"
                 : "=r"(r0), "=r"(r1), "=r"(r2), "=r"(r3) : "r"(addr));
}
__device__ __forceinline__ void mma_f16(float& d0, float& d1, float& d2, float& d3,
                                        uint32_t a0, uint32_t a1, uint32_t a2, uint32_t a3,
                                        uint32_t b0, uint32_t b1) {
    asm volatile(
        "mma.sync.aligned.m16n8k16.row.col.f32.f16.f16.f32 "
        "{%0,%1,%2,%3}, {%4,%5,%6,%7}, {%8,%9}, {%0,%1,%2,%3};"
        : "+f"(d0), "+f"(d1), "+f"(d2), "+f"(d3)
        : "r"(a0), "r"(a1), "r"(a2), "r"(a3), "r"(b0), "r"(b1));
}
__device__ __forceinline__ void cp_async16(uint32_t dst, const void* src) {
    asm volatile("cp.async.cg.shared.global [%0], [%1], 16;" :: "r"(dst), "l"(src));
}
#define CP_COMMIT() asm volatile("cp.async.commit_group;" ::: "memory")
#define CP_WAIT1()  asm volatile("cp.async.wait_group 1;" ::: "memory")

__device__ __forceinline__ uint32_t pack2h(float a, float b) {
    __half ha = __float2half_rn(a), hb = __float2half_rn(b);
    return ((uint32_t)__half_as_ushort(hb) << 16) | __half_as_ushort(ha);
}

// ---------------- main GEMM ----------------
__global__ void __launch_bounds__(NTHREADS, 2)
fiber_gemm_hmma(const float* __restrict__ x, const float* __restrict__ bias,
                float* __restrict__ out) {
    extern __shared__ char smem[];
    const uint32_t sbase = smem_u32(smem);

    const int tid  = threadIdx.x;
    const int lane = tid & 31;
    const int warp = tid >> 5;
    const int wm = warp >> 2;          // 0..1
    const int wn = warp & 3;           // 0..3
    const int bn = blockIdx.x;         // 0..2
    const int bm = blockIdx.y;         // 0..3124

    const float* xblk = x + (size_t)bm * BM * KDIM;
    const __half* gBh = g_Bh + (size_t)bn * BN * KDIM;

    float acc[4][4][4];
    #pragma unroll
    for (int a = 0; a < 4; a++)
        #pragma unroll
        for (int b = 0; b < 4; b++)
            #pragma unroll
            for (int c = 0; c < 4; c++) acc[a][b][c] = 0.f;

    const uint32_t a_lane_off = (uint32_t)((wm * 64 + (lane & 15)) * (SSTR * 2) + (lane >> 4) * 16);
    const uint32_t b_lane_off = (uint32_t)((wn * 32 + ((lane >> 4) << 3) + (lane & 7)) * (SSTR * 2)
                                           + ((lane >> 3) & 1) * 16);

    float4 xr[4];

    auto load_x = [&](int c) {
        #pragma unroll
        for (int it = 0; it < 4; it++) {
            int slot = it * NTHREADS + tid;
            int r = slot >> 3, c4 = (slot & 7) * 4;
            xr[it] = *(const float4*)(xblk + (size_t)r * KDIM + c * BK + c4);
        }
    };
    auto cp_B = [&](int c) {
        uint32_t dBh = sbase + (c % NSTAGES) * STAGE_BYTES + TILE_BYTES;
        #pragma unroll
        for (int it = 0; it < 2; it++) {
            int slot = it * NTHREADS + tid;
            int r = slot >> 2, seg = slot & 3;
            uint32_t doff = (uint32_t)(r * (SSTR * 2) + seg * 16);
            size_t goff = (size_t)r * KDIM + c * BK + seg * 8;
            cp_async16(dBh + doff, gBh + goff);
        }
        CP_COMMIT();
    };
    auto sts_x = [&](int c) {
        uint32_t dAh = sbase + (c % NSTAGES) * STAGE_BYTES;
        #pragma unroll
        for (int it = 0; it < 4; it++) {
            int slot = it * NTHREADS + tid;
            int r = slot >> 3, c4 = (slot & 7) * 4;
            uint32_t h01 = pack2h(xr[it].x, xr[it].y);
            uint32_t h23 = pack2h(xr[it].z, xr[it].w);
            uint32_t doff = (uint32_t)(r * (SSTR * 2) + c4 * 2);
            asm volatile("st.shared.v2.b32 [%0], {%1,%2};" :: "r"(dAh + doff), "r"(h01), "r"(h23));
        }
    };

    // prologue: stage chunks 0 and 1
    cp_B(0);
    cp_B(1);
    load_x(0);
    sts_x(0);
    load_x(1);
    sts_x(1);
    CP_WAIT1();          // B(0) complete; B(1) may still be in flight
    __syncthreads();

    for (int c = 0; c < NCHUNK; c++) {
        const int s = c % NSTAGES;
        if (c + 2 < NCHUNK) cp_B(c + 2);
        if (c + 1 < NCHUNK) load_x(c + 1);

        const uint32_t Ah = sbase + s * STAGE_BYTES;
        const uint32_t Bh = Ah + TILE_BYTES;

        #pragma unroll
        for (int ks = 0; ks < BK / 16; ks++) {
            const uint32_t kso = ks * 32;
            uint32_t af[4][4], bh[2][4];
            #pragma unroll
            for (int mi = 0; mi < 4; mi++)
                ldsm_x4(af[mi][0], af[mi][1], af[mi][2], af[mi][3],
                        Ah + a_lane_off + mi * 16 * (SSTR * 2) + kso);
            #pragma unroll
            for (int pj = 0; pj < 2; pj++)
                ldsm_x4(bh[pj][0], bh[pj][1], bh[pj][2], bh[pj][3],
                        Bh + b_lane_off + pj * 16 * (SSTR * 2) + kso);

            #pragma unroll
            for (int mi = 0; mi < 4; mi++)
                #pragma unroll
                for (int ni = 0; ni < 4; ni++)
                    mma_f16(acc[mi][ni][0], acc[mi][ni][1], acc[mi][ni][2], acc[mi][ni][3],
                            af[mi][0], af[mi][1], af[mi][2], af[mi][3],
                            bh[ni >> 1][(ni & 1) * 2], bh[ni >> 1][(ni & 1) * 2 + 1]);
        }

        if (c + 1 < NCHUNK) sts_x(c + 1);
        CP_WAIT1();      // ensure B(c+1) landed; B(c+2) may remain in flight
        __syncthreads();
    }

    // ---- epilogue: registers -> global (float2 stores) + bias ----
    float* oblk = out + (size_t)bm * BM * NDIM + bn * BN;
    const int r0 = wm * 64 + (lane >> 2);
    const int c0 = wn * 32 + (lane & 3) * 2;
    #pragma unroll
    for (int ni = 0; ni < 4; ni++) {
        const int col = c0 + ni * 8;
        const float b0 = bias[col & 31];
        const float b1 = bias[(col + 1) & 31];
        #pragma unroll
        for (int mi = 0; mi < 4; mi++) {
            const int row = r0 + mi * 16;
            float2 v0 = make_float2(acc[mi][ni][0] + b0, acc[mi][ni][1] + b1);
            float2 v1 = make_float2(acc[mi][ni][2] + b0, acc[mi][ni][3] + b1);
            *(float2*)(oblk + (size_t)row * NDIM + col) = v0;
            *(float2*)(oblk + (size_t)(row + 8) * NDIM + col) = v1;
        }
    }
}

// ---------------------------------------------------------------------------
extern "C" void kernel_launch(void* const* d_in, const int* in_sizes, int n_in,
                              void* d_out, int out_size) {
    const float* x    = (const float*)d_in[0];   // [400000, 384]
    const float* edge = (const float*)d_in[1];   // [12, 12, 3]
    const float* W    = (const float*)d_in[2];   // [1024, 3]
    const float* bias = (const float*)d_in[3];   // [32]
    float* out = (float*)d_out;                  // [400000, 384]

    cudaFuncSetAttribute(fiber_gemm_hmma,
                         cudaFuncAttributeMaxDynamicSharedMemorySize, SMEM_DYN);

    fiber_precompute<<<(NDIM * KDIM + 255) / 256, 256>>>(edge, W);

    dim3 grid(NDIM / BN, BATCH / BM);   // (3, 3125)
    fiber_gemm_hmma<<<grid, NTHREADS, SMEM_DYN>>>(x, bias, out);
}

// round 9
// speedup vs baseline: 2.4500x; 1.2972x over previous
#include <cuda_runtime.h>
#include <cuda_fp16.h>
#include <cstdint>

// FiberConv collapsed to GEMM: C[400000,384] = x[400000,384] @ Bt^T + bias
//   Bt[n=(t*32+o)][k=(s*32+i)] = sum_a edge[t,s,a] * W[o*32+i, a]
// Single-pass fp16 (xh*Bh), rel_err ~2.9e-4 (calibrated R6-R8).
// R9: BK 32 -> 64. Halves sync boundaries (12 -> 6), doubles MMA run length
// between barriers; x register staging split into two half-rounds interleaved
// with the MMA groups to stay under the 128-reg / 2-CTA-per-SM cap.

#define NDIM 384
#define KDIM 384
#define BATCH 400000

#define BM 128
#define BN 128
#define BK 64
#define NTHREADS 256
#define NCHUNK (KDIM / BK)                 // 6

#define SSTR 72                            // padded fp16 row stride (144 bytes)
#define TILE_BYTES (128 * SSTR * 2)        // 18432
#define STAGE_BYTES (2 * TILE_BYTES)       // Ah, Bh = 36864
#define SMEM_DYN (2 * STAGE_BYTES)         // 73728

__device__ __half g_Bh[NDIM * KDIM];

__global__ void fiber_precompute(const float* __restrict__ edge,
                                 const float* __restrict__ W) {
    int idx = blockIdx.x * blockDim.x + threadIdx.x;
    if (idx >= NDIM * KDIM) return;
    int n = idx / KDIM, k = idx % KDIM;
    int t = n >> 5, o = n & 31, s = k >> 5, i = k & 31;
    const float* e = edge + (t * 12 + s) * 3;
    const float* w = W + (o * 32 + i) * 3;
    float v = e[0] * w[0] + e[1] * w[1] + e[2] * w[2];
    g_Bh[idx] = __float2half_rn(v);
}

// ---------------- PTX helpers ----------------
__device__ __forceinline__ uint32_t smem_u32(const void* p) {
    uint32_t a;
    asm("{ .reg .u64 t; cvta.to.shared.u64 t, %1; cvt.u32.u64 %0, t; }" : "=r"(a) : "l"(p));
    return a;
}
__device__ __forceinline__ void ldsm_x4(uint32_t& r0, uint32_t& r1, uint32_t& r2,
                                        uint32_t& r3, uint32_t addr) {
    asm volatile("ldmatrix.sync.aligned.m8n8.x4.shared.b16 {%0,%1,%2,%3}, [%4];"
                 : "=r"(r0), "=r"(r1), "=r"(r2), "=r"(r3) : "r"(addr));
}
__device__ __forceinline__ void mma_f16(float& d0, float& d1, float& d2, float& d3,
                                        uint32_t a0, uint32_t a1, uint32_t a2, uint32_t a3,
                                        uint32_t b0, uint32_t b1) {
    asm volatile(
        "mma.sync.aligned.m16n8k16.row.col.f32.f16.f16.f32 "
        "{%0,%1,%2,%3}, {%4,%5,%6,%7}, {%8,%9}, {%0,%1,%2,%3};"
        : "+f"(d0), "+f"(d1), "+f"(d2), "+f"(d3)
        : "r"(a0), "r"(a1), "r"(a2), "r"(a3), "r"(b0), "r"(b1));
}
__device__ __forceinline__ void cp_async16(uint32_t dst, const void* src) {
    asm volatile("cp.async.cg.shared.global [%0], [%1], 16;" :: "r"(dst), "l"(src));
}
#define CP_COMMIT() asm volatile("cp.async.commit_group;" ::: "memory")
#define CP_WAIT0()  asm volatile("cp.async.wait_group 0;" ::: "memory")

__device__ __forceinline__ uint32_t pack2h(float a, float b) {
    __half ha = __float2half_rn(a), hb = __float2half_rn(b);
    return ((uint32_t)__half_as_ushort(hb) << 16) | __half_as_ushort(ha);
}

// ---------------- main GEMM ----------------
__global__ void __launch_bounds__(NTHREADS, 2)
fiber_gemm_hmma(const float* __restrict__ x, const float* __restrict__ bias,
                float* __restrict__ out) {
    extern __shared__ char smem[];
    const uint32_t sbase = smem_u32(smem);

    const int tid  = threadIdx.x;
    const int lane = tid & 31;
    const int warp = tid >> 5;
    const int wm = warp >> 2;          // 0..1
    const int wn = warp & 3;           // 0..3
    const int bn = blockIdx.x;         // 0..2
    const int bm = blockIdx.y;         // 0..3124

    const float* xblk = x + (size_t)bm * BM * KDIM;
    const __half* gBh = g_Bh + (size_t)bn * BN * KDIM;

    float acc[4][4][4];
    #pragma unroll
    for (int a = 0; a < 4; a++)
        #pragma unroll
        for (int b = 0; b < 4; b++)
            #pragma unroll
            for (int c = 0; c < 4; c++) acc[a][b][c] = 0.f;

    const uint32_t a_lane_off = (uint32_t)((wm * 64 + (lane & 15)) * (SSTR * 2) + (lane >> 4) * 16);
    const uint32_t b_lane_off = (uint32_t)((wn * 32 + ((lane >> 4) << 3) + (lane & 7)) * (SSTR * 2)
                                           + ((lane >> 3) & 1) * 16);

    float4 xr[4];   // half-chunk staging (4 float4/thread)

    // half h of chunk c: 64 rows x 64 cols fp32 -> rows [h*64, h*64+64)
    auto load_xh = [&](int c, int h) {
        #pragma unroll
        for (int it = 0; it < 4; it++) {
            int slot = it * NTHREADS + tid;          // 0..1023
            int r = h * 64 + (slot >> 4);            // 16 float4 per row
            int c4 = (slot & 15) * 4;
            xr[it] = *(const float4*)(xblk + (size_t)r * KDIM + c * BK + c4);
        }
    };
    auto sts_xh = [&](int c, int h) {
        uint32_t dAh = sbase + (c & 1) * STAGE_BYTES;
        #pragma unroll
        for (int it = 0; it < 4; it++) {
            int slot = it * NTHREADS + tid;
            int r = h * 64 + (slot >> 4);
            int c4 = (slot & 15) * 4;
            uint32_t h01 = pack2h(xr[it].x, xr[it].y);
            uint32_t h23 = pack2h(xr[it].z, xr[it].w);
            uint32_t doff = (uint32_t)(r * (SSTR * 2) + c4 * 2);
            asm volatile("st.shared.v2.b32 [%0], {%1,%2};" :: "r"(dAh + doff), "r"(h01), "r"(h23));
        }
    };
    auto cp_B = [&](int c) {
        uint32_t dBh = sbase + (c & 1) * STAGE_BYTES + TILE_BYTES;
        #pragma unroll
        for (int it = 0; it < 4; it++) {
            int slot = it * NTHREADS + tid;          // 0..1023
            int r = slot >> 3, seg = slot & 7;       // 8 x 16B per row
            uint32_t doff = (uint32_t)(r * (SSTR * 2) + seg * 16);
            size_t goff = (size_t)r * KDIM + c * BK + seg * 8;
            cp_async16(dBh + doff, gBh + goff);
        }
        CP_COMMIT();
    };

    // MMA group over ks slices [k0, k1) of the current stage
    auto mma_group = [&](int c, int k0, int k1) {
        const uint32_t Ah = sbase + (c & 1) * STAGE_BYTES;
        const uint32_t Bh = Ah + TILE_BYTES;
        #pragma unroll
        for (int ks = k0; ks < k1; ks++) {
            const uint32_t kso = ks * 32;
            uint32_t af[4][4], bh[2][4];
            #pragma unroll
            for (int mi = 0; mi < 4; mi++)
                ldsm_x4(af[mi][0], af[mi][1], af[mi][2], af[mi][3],
                        Ah + a_lane_off + mi * 16 * (SSTR * 2) + kso);
            #pragma unroll
            for (int pj = 0; pj < 2; pj++)
                ldsm_x4(bh[pj][0], bh[pj][1], bh[pj][2], bh[pj][3],
                        Bh + b_lane_off + pj * 16 * (SSTR * 2) + kso);
            #pragma unroll
            for (int mi = 0; mi < 4; mi++)
                #pragma unroll
                for (int ni = 0; ni < 4; ni++)
                    mma_f16(acc[mi][ni][0], acc[mi][ni][1], acc[mi][ni][2], acc[mi][ni][3],
                            af[mi][0], af[mi][1], af[mi][2], af[mi][3],
                            bh[ni >> 1][(ni & 1) * 2], bh[ni >> 1][(ni & 1) * 2 + 1]);
        }
    };

    // prologue: stage chunk 0
    cp_B(0);
    load_xh(0, 0); sts_xh(0, 0);
    load_xh(0, 1); sts_xh(0, 1);
    CP_WAIT0();
    __syncthreads();

    for (int c = 0; c < NCHUNK; c++) {
        if (c + 1 < NCHUNK) {
            cp_B(c + 1);
            load_xh(c + 1, 0);
            mma_group(c, 0, 2);
            sts_xh(c + 1, 0);
            load_xh(c + 1, 1);
            mma_group(c, 2, 4);
            sts_xh(c + 1, 1);
            CP_WAIT0();
        } else {
            mma_group(c, 0, 4);
        }
        __syncthreads();
    }

    // ---- epilogue: registers -> global (float2 stores) + bias ----
    float* oblk = out + (size_t)bm * BM * NDIM + bn * BN;
    const int r0 = wm * 64 + (lane >> 2);
    const int c0 = wn * 32 + (lane & 3) * 2;
    #pragma unroll
    for (int ni = 0; ni < 4; ni++) {
        const int col = c0 + ni * 8;
        const float b0 = bias[col & 31];
        const float b1 = bias[(col + 1) & 31];
        #pragma unroll
        for (int mi = 0; mi < 4; mi++) {
            const int row = r0 + mi * 16;
            float2 v0 = make_float2(acc[mi][ni][0] + b0, acc[mi][ni][1] + b1);
            float2 v1 = make_float2(acc[mi][ni][2] + b0, acc[mi][ni][3] + b1);
            *(float2*)(oblk + (size_t)row * NDIM + col) = v0;
            *(float2*)(oblk + (size_t)(row + 8) * NDIM + col) = v1;
        }
    }
}

// ---------------------------------------------------------------------------
extern "C" void kernel_launch(void* const* d_in, const int* in_sizes, int n_in,
                              void* d_out, int out_size) {
    const float* x    = (const float*)d_in[0];   // [400000, 384]
    const float* edge = (const float*)d_in[1];   // [12, 12, 3]
    const float* W    = (const float*)d_in[2];   // [1024, 3]
    const float* bias = (const float*)d_in[3];   // [32]
    float* out = (float*)d_out;                  // [400000, 384]

    cudaFuncSetAttribute(fiber_gemm_hmma,
                         cudaFuncAttributeMaxDynamicSharedMemorySize, SMEM_DYN);

    fiber_precompute<<<(NDIM * KDIM + 255) / 256, 256>>>(edge, W);

    dim3 grid(NDIM / BN, BATCH / BM);   // (3, 3125)
    fiber_gemm_hmma<<<grid, NTHREADS, SMEM_DYN>>>(x, bias, out);
}